// round 1
// baseline (speedup 1.0000x reference)
#include <cuda_runtime.h>
#include <cstdint>

#define M_DIM 16384
#define N_DIM 4096
#define K_DIM 4096
#define R_DIM 16

// ---- device scratch (no allocations allowed) ----
__device__ float g_W2 [N_DIM * R_DIM];   // O*U*S
__device__ float g_W2s[N_DIM * R_DIM];   // scale * O*U*S   (epilogue-ready)
__device__ float g_G  [R_DIM * R_DIM];   // V V^T
__device__ float g_d  [N_DIM * R_DIM];   // base_weight @ V^T
__device__ float g_nb [N_DIM];           // ||base row||^2
__device__ float g_t  [M_DIM * R_DIM];   // x @ V^T
__device__ float g_sm1[N_DIM];           // scale - 1

__device__ __forceinline__ float to_tf32(float x) {
  uint32_t u;
  asm("cvt.rna.tf32.f32 %0, %1;" : "=r"(u) : "f"(x));
  return __uint_as_float(u);
}

// ============================================================
// k_prep: W2[o,r] = O[o]*U[o,r]*S[r]  (blocks 0..255)
//         G = V V^T (16x16)           (block 256)
// ============================================================
__global__ void k_prep(const float* __restrict__ U, const float* __restrict__ V,
                       const float* __restrict__ S, const float* __restrict__ O) {
  if (blockIdx.x < 256) {
    int idx = blockIdx.x * 256 + threadIdx.x;      // 0..65535
    int o = idx >> 4, r = idx & 15;
    g_W2[idx] = O[o] * U[idx] * S[r];
  } else {
    int r  = threadIdx.x >> 4;
    int r2 = threadIdx.x & 15;
    const float4* va = (const float4*)(V + r  * K_DIM);
    const float4* vb = (const float4*)(V + r2 * K_DIM);
    float s = 0.f;
    for (int i = 0; i < K_DIM / 4; ++i) {
      float4 a = va[i], b = vb[i];
      s += a.x * b.x + a.y * b.y + a.z * b.z + a.w * b.w;
    }
    g_G[threadIdx.x] = s;
  }
}

// ============================================================
// k_rowdot: dot[m,r] = sum_i in[m,i] * V[r,i]
// MODE 0: in = base_weight -> g_d, g_nb (row norm^2)
// MODE 1: in = x           -> g_t
// 256 threads, 32 rows/block (4 per warp), V chunked through smem.
// ============================================================
template <int MODE>
__global__ void k_rowdot(const float* __restrict__ in, const float* __restrict__ V) {
  __shared__ float vs[R_DIM * 512];
  const int tid = threadIdx.x, lane = tid & 31, warp = tid >> 5;
  const int m0 = blockIdx.x * 32 + warp * 4;
  float acc[4][16];
  float nacc[4] = {0.f, 0.f, 0.f, 0.f};
#pragma unroll
  for (int m = 0; m < 4; ++m)
#pragma unroll
    for (int r = 0; r < 16; ++r) acc[m][r] = 0.f;

  for (int kc = 0; kc < K_DIM; kc += 512) {
    __syncthreads();
    for (int i = tid; i < R_DIM * 128; i += 256) {   // 2048 float4 groups
      int r = i >> 7, c4 = (i & 127) << 2;
      *(float4*)&vs[r * 512 + c4] = *(const float4*)&V[r * K_DIM + kc + c4];
    }
    __syncthreads();
    for (int i = lane; i < 512; i += 32) {
      float x0 = in[(m0 + 0) * K_DIM + kc + i];
      float x1 = in[(m0 + 1) * K_DIM + kc + i];
      float x2 = in[(m0 + 2) * K_DIM + kc + i];
      float x3 = in[(m0 + 3) * K_DIM + kc + i];
      if (MODE == 0) {
        nacc[0] += x0 * x0; nacc[1] += x1 * x1;
        nacc[2] += x2 * x2; nacc[3] += x3 * x3;
      }
#pragma unroll
      for (int r = 0; r < 16; ++r) {
        float vv = vs[r * 512 + i];
        acc[0][r] += x0 * vv; acc[1][r] += x1 * vv;
        acc[2][r] += x2 * vv; acc[3][r] += x3 * vv;
      }
    }
  }
#pragma unroll
  for (int m = 0; m < 4; ++m) {
#pragma unroll
    for (int r = 0; r < 16; ++r) {
      float v = acc[m][r];
#pragma unroll
      for (int off = 16; off; off >>= 1) v += __shfl_xor_sync(0xffffffffu, v, off);
      acc[m][r] = v;
    }
    if (MODE == 0) {
      float v = nacc[m];
#pragma unroll
      for (int off = 16; off; off >>= 1) v += __shfl_xor_sync(0xffffffffu, v, off);
      nacc[m] = v;
    }
  }
  if (lane == 0) {
    float* dout = (MODE == 0) ? g_d : g_t;
#pragma unroll
    for (int m = 0; m < 4; ++m) {
#pragma unroll
      for (int r = 0; r < 16; ++r) dout[(m0 + m) * 16 + r] = acc[m][r];
      if (MODE == 0) g_nb[m0 + m] = nacc[m];
    }
  }
}

// ============================================================
// k_scale: norm^2 = nb + 2*w2.d + w2^T G w2 ; scale = mag/sqrt(norm^2)
// ============================================================
__global__ void k_scale(const float* __restrict__ mag) {
  int o = blockIdx.x * 256 + threadIdx.x;
  float w2[16];
#pragma unroll
  for (int r = 0; r < 16; ++r) w2[r] = g_W2[o * 16 + r];
  float n2 = g_nb[o];
#pragma unroll
  for (int r = 0; r < 16; ++r) n2 += 2.f * w2[r] * g_d[o * 16 + r];
#pragma unroll
  for (int r = 0; r < 16; ++r) {
    float gr = 0.f;
#pragma unroll
    for (int r2 = 0; r2 < 16; ++r2) gr += g_G[r * 16 + r2] * w2[r2];
    n2 += w2[r] * gr;
  }
  float sc = mag[o] / sqrtf(n2);
  g_sm1[o] = sc - 1.f;
#pragma unroll
  for (int r = 0; r < 16; ++r) g_W2s[o * 16 + r] = sc * w2[r];
}

// ============================================================
// k_gemm: out[m,n] = (scale[n]-1) * (x@W^T)[m,n] + sum_r t[m,r]*W2s[n,r]
// 3xTF32 warp MMA (m16n8k8), BM=BN=128, BK=32, 8 warps (2x4), warp 64x32.
// Smem tiles stored hi/lo pre-split, stride 36 floats => conflict-free
// fragment loads AND 16B-aligned float4 stores. Double-buffered.
// ============================================================
#define BK 32
#define TSTR 36
#define TILE_F (128 * TSTR)

#define MMA_TF32(d, a, b)                                                   \
  asm volatile("mma.sync.aligned.m16n8k8.row.col.f32.tf32.tf32.f32 "        \
               "{%0,%1,%2,%3}, {%4,%5,%6,%7}, {%8,%9}, {%0,%1,%2,%3};\n"    \
               : "+f"(d[0]), "+f"(d[1]), "+f"(d[2]), "+f"(d[3])             \
               : "r"(a[0]), "r"(a[1]), "r"(a[2]), "r"(a[3]),                \
                 "r"(b[0]), "r"(b[1]))

__device__ __forceinline__ void split_store(float* dst_hi, int off, float4 v) {
  float4 h, l;
  h.x = to_tf32(v.x); h.y = to_tf32(v.y); h.z = to_tf32(v.z); h.w = to_tf32(v.w);
  l.x = to_tf32(v.x - h.x); l.y = to_tf32(v.y - h.y);
  l.z = to_tf32(v.z - h.z); l.w = to_tf32(v.w - h.w);
  *(float4*)(dst_hi + off)          = h;
  *(float4*)(dst_hi + TILE_F + off) = l;
}

__global__ void __launch_bounds__(256, 1)
k_gemm(const float* __restrict__ A, const float* __restrict__ B,
       float* __restrict__ out) {
  extern __shared__ float sm[];
  const int tid  = threadIdx.x;
  const int lane = tid & 31;
  const int warp = tid >> 5;
  const int m_base = (warp >> 2) * 64;
  const int n_base = (warp & 3) * 32;
  const int bM = blockIdx.y * 128;
  const int bN = blockIdx.x * 128;

  const int lr = tid >> 3;         // 0..31
  const int lc = (tid & 7) << 2;   // 0,4..28

  float acc[4][4][4];
#pragma unroll
  for (int i = 0; i < 4; ++i)
#pragma unroll
    for (int j = 0; j < 4; ++j)
#pragma unroll
      for (int e = 0; e < 4; ++e) acc[i][j][e] = 0.f;

  const float* gA = A + (bM + lr) * K_DIM + lc;
  const float* gB = B + (bN + lr) * K_DIM + lc;

  float4 ra[4], rb[4];
#pragma unroll
  for (int j = 0; j < 4; ++j) {
    ra[j] = *(const float4*)(gA + j * 32 * K_DIM);
    rb[j] = *(const float4*)(gB + j * 32 * K_DIM);
  }
  {
    float* dbuf = sm;  // buffer 0
#pragma unroll
    for (int j = 0; j < 4; ++j) {
      int off = (lr + 32 * j) * TSTR + lc;
      split_store(dbuf, off, ra[j]);
      split_store(dbuf + 2 * TILE_F, off, rb[j]);
    }
  }
  __syncthreads();

  const int NKT = K_DIM / BK;  // 128
  for (int kt = 0; kt < NKT; ++kt) {
    const float* buf = sm + (kt & 1) * (4 * TILE_F);
    if (kt + 1 < NKT) {
      int ko = (kt + 1) * BK;
#pragma unroll
      for (int j = 0; j < 4; ++j) {
        ra[j] = *(const float4*)(gA + j * 32 * K_DIM + ko);
        rb[j] = *(const float4*)(gB + j * 32 * K_DIM + ko);
      }
    }
    const float* sAh = buf;
    const float* sBh = buf + 2 * TILE_F;
#pragma unroll
    for (int kk = 0; kk < BK; kk += 8) {
      uint32_t ah[4][4], al[4][4], bh[4][2], bl[4][2];
#pragma unroll
      for (int mt = 0; mt < 4; ++mt) {
        int off = (m_base + mt * 16 + (lane >> 2)) * TSTR + kk + (lane & 3);
        ah[mt][0] = __float_as_uint(sAh[off]);
        ah[mt][1] = __float_as_uint(sAh[off + 8 * TSTR]);
        ah[mt][2] = __float_as_uint(sAh[off + 4]);
        ah[mt][3] = __float_as_uint(sAh[off + 8 * TSTR + 4]);
        al[mt][0] = __float_as_uint(sAh[TILE_F + off]);
        al[mt][1] = __float_as_uint(sAh[TILE_F + off + 8 * TSTR]);
        al[mt][2] = __float_as_uint(sAh[TILE_F + off + 4]);
        al[mt][3] = __float_as_uint(sAh[TILE_F + off + 8 * TSTR + 4]);
      }
#pragma unroll
      for (int nt = 0; nt < 4; ++nt) {
        int off = (n_base + nt * 8 + (lane >> 2)) * TSTR + kk + (lane & 3);
        bh[nt][0] = __float_as_uint(sBh[off]);
        bh[nt][1] = __float_as_uint(sBh[off + 4]);
        bl[nt][0] = __float_as_uint(sBh[TILE_F + off]);
        bl[nt][1] = __float_as_uint(sBh[TILE_F + off + 4]);
      }
#pragma unroll
      for (int mt = 0; mt < 4; ++mt)
#pragma unroll
        for (int nt = 0; nt < 4; ++nt) {
          MMA_TF32(acc[mt][nt], ah[mt], bh[nt]);
          MMA_TF32(acc[mt][nt], al[mt], bh[nt]);
          MMA_TF32(acc[mt][nt], ah[mt], bl[nt]);
        }
    }
    if (kt + 1 < NKT) {
      float* dbuf = sm + ((kt + 1) & 1) * (4 * TILE_F);
#pragma unroll
      for (int j = 0; j < 4; ++j) {
        int off = (lr + 32 * j) * TSTR + lc;
        split_store(dbuf, off, ra[j]);
        split_store(dbuf + 2 * TILE_F, off, rb[j]);
      }
    }
    __syncthreads();
  }

  // ---- fused DoRA epilogue ----
  float* st = sm;                   // t tile   [128][17]
  float* sw = sm + 128 * 17;        // W2s tile [128][17]
  float* ss = sm + 2 * 128 * 17;    // scale-1  [128]
  for (int i = tid; i < 2048; i += 256) st[(i >> 4) * 17 + (i & 15)] = g_t  [bM * 16 + i];
  for (int i = tid; i < 2048; i += 256) sw[(i >> 4) * 17 + (i & 15)] = g_W2s[bN * 16 + i];
  if (tid < 128) ss[tid] = g_sm1[bN + tid];
  __syncthreads();

#pragma unroll
  for (int nt = 0; nt < 4; ++nt) {
    int c = n_base + nt * 8 + 2 * (lane & 3);
    float s0 = ss[c], s1 = ss[c + 1];
#pragma unroll
    for (int mt = 0; mt < 4; ++mt) {
      acc[mt][nt][0] *= s0; acc[mt][nt][1] *= s1;
      acc[mt][nt][2] *= s0; acc[mt][nt][3] *= s1;
    }
  }
#pragma unroll
  for (int r = 0; r < 16; ++r) {
    float tr[8], wr[8];
#pragma unroll
    for (int mt = 0; mt < 4; ++mt) {
      tr[mt * 2]     = st[(m_base + mt * 16 +     (lane >> 2)) * 17 + r];
      tr[mt * 2 + 1] = st[(m_base + mt * 16 + 8 + (lane >> 2)) * 17 + r];
    }
#pragma unroll
    for (int nt = 0; nt < 4; ++nt) {
      wr[nt * 2]     = sw[(n_base + nt * 8 + 2 * (lane & 3))     * 17 + r];
      wr[nt * 2 + 1] = sw[(n_base + nt * 8 + 2 * (lane & 3) + 1) * 17 + r];
    }
#pragma unroll
    for (int mt = 0; mt < 4; ++mt)
#pragma unroll
      for (int nt = 0; nt < 4; ++nt) {
        acc[mt][nt][0] += tr[mt * 2]     * wr[nt * 2];
        acc[mt][nt][1] += tr[mt * 2]     * wr[nt * 2 + 1];
        acc[mt][nt][2] += tr[mt * 2 + 1] * wr[nt * 2];
        acc[mt][nt][3] += tr[mt * 2 + 1] * wr[nt * 2 + 1];
      }
  }
#pragma unroll
  for (int mt = 0; mt < 4; ++mt)
#pragma unroll
    for (int h = 0; h < 2; ++h) {
      int gm = bM + m_base + mt * 16 + h * 8 + (lane >> 2);
#pragma unroll
      for (int nt = 0; nt < 4; ++nt) {
        int gn = bN + n_base + nt * 8 + 2 * (lane & 3);
        float2 v = make_float2(acc[mt][nt][h * 2], acc[mt][nt][h * 2 + 1]);
        *(float2*)(out + (size_t)gm * N_DIM + gn) = v;
      }
    }
}

// ============================================================
extern "C" void kernel_launch(void* const* d_in, const int* in_sizes, int n_in,
                              void* d_out, int out_size) {
  (void)in_sizes; (void)n_in; (void)out_size;
  const float* x   = (const float*)d_in[0];
  const float* U   = (const float*)d_in[1];
  const float* V   = (const float*)d_in[2];
  const float* S   = (const float*)d_in[3];
  const float* O   = (const float*)d_in[4];
  const float* mag = (const float*)d_in[5];
  const float* W   = (const float*)d_in[6];
  float* out = (float*)d_out;

  const int smem_gemm = 2 * 4 * TILE_F * (int)sizeof(float);  // 147456
  cudaFuncSetAttribute(k_gemm, cudaFuncAttributeMaxDynamicSharedMemorySize, smem_gemm);

  k_prep<<<257, 256>>>(U, V, S, O);
  k_rowdot<0><<<N_DIM / 32, 256>>>(W, V);     // g_d, g_nb
  k_scale<<<N_DIM / 256, 256>>>(mag);         // g_sm1, g_W2s
  k_rowdot<1><<<M_DIM / 32, 256>>>(x, V);     // g_t
  k_gemm<<<dim3(N_DIM / 128, M_DIM / 128), 256, smem_gemm>>>(x, W, out);
}

// round 3
// speedup vs baseline: 1.7983x; 1.7983x over previous
#include <cuda_runtime.h>
#include <cuda_fp16.h>
#include <cstdint>

#define M_DIM 16384
#define N_DIM 4096
#define K_DIM 4096
#define R_DIM 16

// ---- device scratch (module-load allocated; no runtime allocs) ----
__device__ float g_W2 [N_DIM * R_DIM];
__device__ float g_W2s[N_DIM * R_DIM];
__device__ float g_G  [R_DIM * R_DIM];
__device__ float g_d  [N_DIM * R_DIM];
__device__ float g_nb [N_DIM];
__device__ float g_t  [M_DIM * R_DIM];
__device__ float g_sm1[N_DIM];
// fp16 hi/lo split planes
__device__ __half g_xh_h[(size_t)M_DIM * K_DIM];
__device__ __half g_xl_h[(size_t)M_DIM * K_DIM];
__device__ __half g_wh_h[(size_t)N_DIM * K_DIM];
__device__ __half g_wl_h[(size_t)N_DIM * K_DIM];

__device__ __forceinline__ uint32_t smem_u32(const void* p) {
  uint32_t a;
  asm("{ .reg .u64 t; cvta.to.shared.u64 t, %1; cvt.u32.u64 %0, t; }" : "=r"(a) : "l"(p));
  return a;
}
__device__ __forceinline__ void cpa16(uint32_t dst, const void* src) {
  asm volatile("cp.async.cg.shared.global [%0], [%1], 16;" :: "r"(dst), "l"(src) : "memory");
}

#define LDMX4(r, addr)                                                        \
  asm volatile("ldmatrix.sync.aligned.m8n8.x4.shared.b16 {%0,%1,%2,%3}, [%4];"\
               : "=r"((r)[0]), "=r"((r)[1]), "=r"((r)[2]), "=r"((r)[3])       \
               : "r"(addr))

#define MMA16816(d, a, b)                                                     \
  asm volatile("mma.sync.aligned.m16n8k16.row.col.f32.f16.f16.f32 "           \
               "{%0,%1,%2,%3}, {%4,%5,%6,%7}, {%8,%9}, {%0,%1,%2,%3};"        \
               : "+f"((d)[0]), "+f"((d)[1]), "+f"((d)[2]), "+f"((d)[3])       \
               : "r"((a)[0]), "r"((a)[1]), "r"((a)[2]), "r"((a)[3]),          \
                 "r"((b)[0]), "r"((b)[1]))

// ============================================================
// k_split_h: fp32 -> (fp16 hi, fp16 lo) planes, 8 elems/thread
// ============================================================
template <int WHICH>  // 0: x -> g_x*_h ; 1: W -> g_w*_h
__global__ void k_split_h(const float* __restrict__ in, int n8) {
  __half* hi = WHICH ? g_wh_h : g_xh_h;
  __half* lo = WHICH ? g_wl_h : g_xl_h;
  int i = blockIdx.x * blockDim.x + threadIdx.x;
  if (i >= n8) return;
  float4 v0 = ((const float4*)in)[2 * i];
  float4 v1 = ((const float4*)in)[2 * i + 1];
  float xs[8] = {v0.x, v0.y, v0.z, v0.w, v1.x, v1.y, v1.z, v1.w};
  union { __half h[8]; uint4 u; } H, L;
#pragma unroll
  for (int j = 0; j < 8; ++j) {
    H.h[j] = __float2half_rn(xs[j]);
    L.h[j] = __float2half_rn(xs[j] - __half2float(H.h[j]));
  }
  ((uint4*)hi)[i] = H.u;
  ((uint4*)lo)[i] = L.u;
}

// ============================================================
// small prep kernels (from R1, correct)
// ============================================================
__global__ void k_prep(const float* __restrict__ U, const float* __restrict__ V,
                       const float* __restrict__ S, const float* __restrict__ O) {
  if (blockIdx.x < 256) {
    int idx = blockIdx.x * 256 + threadIdx.x;
    int o = idx >> 4, r = idx & 15;
    g_W2[idx] = O[o] * U[idx] * S[r];
  } else {
    int r  = threadIdx.x >> 4;
    int r2 = threadIdx.x & 15;
    const float4* va = (const float4*)(V + r  * K_DIM);
    const float4* vb = (const float4*)(V + r2 * K_DIM);
    float s = 0.f;
    for (int i = 0; i < K_DIM / 4; ++i) {
      float4 a = va[i], b = vb[i];
      s += a.x * b.x + a.y * b.y + a.z * b.z + a.w * b.w;
    }
    g_G[threadIdx.x] = s;
  }
}

template <int MODE>
__global__ void k_rowdot(const float* __restrict__ in, const float* __restrict__ V) {
  __shared__ float vs[R_DIM * 512];
  const int tid = threadIdx.x, lane = tid & 31, warp = tid >> 5;
  const int m0 = blockIdx.x * 32 + warp * 4;
  float acc[4][16];
  float nacc[4] = {0.f, 0.f, 0.f, 0.f};
#pragma unroll
  for (int m = 0; m < 4; ++m)
#pragma unroll
    for (int r = 0; r < 16; ++r) acc[m][r] = 0.f;

  for (int kc = 0; kc < K_DIM; kc += 512) {
    __syncthreads();
    for (int i = tid; i < R_DIM * 128; i += 256) {
      int r = i >> 7, c4 = (i & 127) << 2;
      *(float4*)&vs[r * 512 + c4] = *(const float4*)&V[r * K_DIM + kc + c4];
    }
    __syncthreads();
    for (int i = lane; i < 512; i += 32) {
      float x0 = in[(size_t)(m0 + 0) * K_DIM + kc + i];
      float x1 = in[(size_t)(m0 + 1) * K_DIM + kc + i];
      float x2 = in[(size_t)(m0 + 2) * K_DIM + kc + i];
      float x3 = in[(size_t)(m0 + 3) * K_DIM + kc + i];
      if (MODE == 0) {
        nacc[0] += x0 * x0; nacc[1] += x1 * x1;
        nacc[2] += x2 * x2; nacc[3] += x3 * x3;
      }
#pragma unroll
      for (int r = 0; r < 16; ++r) {
        float vv = vs[r * 512 + i];
        acc[0][r] += x0 * vv; acc[1][r] += x1 * vv;
        acc[2][r] += x2 * vv; acc[3][r] += x3 * vv;
      }
    }
  }
#pragma unroll
  for (int m = 0; m < 4; ++m) {
#pragma unroll
    for (int r = 0; r < 16; ++r) {
      float v = acc[m][r];
#pragma unroll
      for (int off = 16; off; off >>= 1) v += __shfl_xor_sync(0xffffffffu, v, off);
      acc[m][r] = v;
    }
    if (MODE == 0) {
      float v = nacc[m];
#pragma unroll
      for (int off = 16; off; off >>= 1) v += __shfl_xor_sync(0xffffffffu, v, off);
      nacc[m] = v;
    }
  }
  if (lane == 0) {
    float* dout = (MODE == 0) ? g_d : g_t;
#pragma unroll
    for (int m = 0; m < 4; ++m) {
#pragma unroll
      for (int r = 0; r < 16; ++r) dout[(m0 + m) * 16 + r] = acc[m][r];
      if (MODE == 0) g_nb[m0 + m] = nacc[m];
    }
  }
}

__global__ void k_scale(const float* __restrict__ mag) {
  int o = blockIdx.x * 256 + threadIdx.x;
  float w2[16];
#pragma unroll
  for (int r = 0; r < 16; ++r) w2[r] = g_W2[o * 16 + r];
  float n2 = g_nb[o];
#pragma unroll
  for (int r = 0; r < 16; ++r) n2 += 2.f * w2[r] * g_d[o * 16 + r];
#pragma unroll
  for (int r = 0; r < 16; ++r) {
    float gr = 0.f;
#pragma unroll
    for (int r2 = 0; r2 < 16; ++r2) gr += g_G[r * 16 + r2] * w2[r2];
    n2 += w2[r] * gr;
  }
  float sc = mag[o] / sqrtf(n2);
  g_sm1[o] = sc - 1.f;
#pragma unroll
  for (int r = 0; r < 16; ++r) g_W2s[o * 16 + r] = sc * w2[r];
}

// ============================================================
// k_gemm_h: 3xFP16 mma.sync m16n8k16, BM=256 BN=128 BK=64,
// cp.async double-buffered, ldmatrix frags, fused DoRA epilogue.
// ============================================================
#define BMt 256
#define BNt 128
#define BKh 64
#define NKT (K_DIM / BKh)            // 64
#define LSTR 72                      // halfs per smem row (144B, 16B-mult, bank step 4)
#define A_PLANE_H (256 * LSTR)       // 18432 halfs
#define B_PLANE_H (128 * LSTR)       // 9216  halfs
#define STAGE_H (2 * A_PLANE_H + 2 * B_PLANE_H)   // 55296 halfs
#define GEMM_SMEM (2 * STAGE_H * 2)  // 221184 bytes

__global__ void __launch_bounds__(256, 1) k_gemm_h(float* __restrict__ out) {
  extern __shared__ __align__(16) __half hsm[];
  const int tid  = threadIdx.x;
  const int lane = tid & 31;
  const int warp = tid >> 5;
  const int m_base = (warp >> 1) * 64;   // 4 warps over M
  const int n_base = (warp & 1) * 64;    // 2 warps over N
  const int bM = blockIdx.y * BMt;
  const int bN = blockIdx.x * BNt;
  const uint32_t smb = smem_u32(hsm);

  float acc[4][8][4];
#pragma unroll
  for (int i = 0; i < 4; ++i)
#pragma unroll
    for (int j = 0; j < 8; ++j)
#pragma unroll
      for (int e = 0; e < 4; ++e) acc[i][j][e] = 0.f;

  auto load_stage = [&](int s, int kt) {
    const int k0 = kt * BKh;
    const uint32_t base = smb + (uint32_t)s * STAGE_H * 2;
#pragma unroll
    for (int ci = 0; ci < 24; ++ci) {
      const int c = ci * 256 + tid;          // 0..6143
      const __half* src;
      uint32_t dst;
      if (c < 4096) {                         // A planes (hi, lo)
        const int pl = c >> 11, i = c & 2047, row = i >> 3, q = i & 7;
        src = (pl ? g_xl_h : g_xh_h) + (size_t)(bM + row) * K_DIM + k0 + q * 8;
        dst = base + (uint32_t)(pl * A_PLANE_H + row * LSTR + q * 8) * 2;
      } else {                                // B planes (hi, lo)
        const int cb = c - 4096, pl = cb >> 10, i = cb & 1023, row = i >> 3, q = i & 7;
        src = (pl ? g_wl_h : g_wh_h) + (size_t)(bN + row) * K_DIM + k0 + q * 8;
        dst = base + (uint32_t)(2 * A_PLANE_H + pl * B_PLANE_H + row * LSTR + q * 8) * 2;
      }
      cpa16(dst, src);
    }
  };

  load_stage(0, 0);
  asm volatile("cp.async.commit_group;" ::: "memory");

  for (int kt = 0; kt < NKT; ++kt) {
    if (kt + 1 < NKT) load_stage((kt + 1) & 1, kt + 1);
    asm volatile("cp.async.commit_group;" ::: "memory");
    asm volatile("cp.async.wait_group 1;" ::: "memory");
    __syncthreads();

    const uint32_t sbase = smb + (uint32_t)(kt & 1) * STAGE_H * 2;
    const uint32_t aB  = sbase;
    const uint32_t alB = sbase + A_PLANE_H * 2;
    const uint32_t bB  = sbase + 2 * A_PLANE_H * 2;
    const uint32_t blB = bB + B_PLANE_H * 2;

    const int arow = (lane & 15);
    const int acol = (lane >> 4) << 3;
    const int brow = (lane & 7) + ((lane >> 4) << 3);
    const int bcol = ((lane >> 3) & 1) << 3;

#pragma unroll
    for (int kk = 0; kk < 4; ++kk) {
      const int kof = kk * 16;
      uint32_t ah[4][4], al[4][4], bh[8][2], bl[8][2];
#pragma unroll
      for (int mt = 0; mt < 4; ++mt) {
        const uint32_t off = (uint32_t)((m_base + mt * 16 + arow) * LSTR + kof + acol) * 2;
        LDMX4(ah[mt], aB + off);
        LDMX4(al[mt], alB + off);
      }
#pragma unroll
      for (int p = 0; p < 4; ++p) {
        const uint32_t off = (uint32_t)((n_base + p * 16 + brow) * LSTR + kof + bcol) * 2;
        uint32_t r[4];
        LDMX4(r, bB + off);
        bh[2 * p][0] = r[0]; bh[2 * p][1] = r[1];
        bh[2 * p + 1][0] = r[2]; bh[2 * p + 1][1] = r[3];
        LDMX4(r, blB + off);
        bl[2 * p][0] = r[0]; bl[2 * p][1] = r[1];
        bl[2 * p + 1][0] = r[2]; bl[2 * p + 1][1] = r[3];
      }
#pragma unroll
      for (int mt = 0; mt < 4; ++mt)
#pragma unroll
        for (int nt = 0; nt < 8; ++nt) {
          MMA16816(acc[mt][nt], ah[mt], bh[nt]);
          MMA16816(acc[mt][nt], al[mt], bh[nt]);
          MMA16816(acc[mt][nt], ah[mt], bl[nt]);
        }
    }
    __syncthreads();
  }

  // ---------------- fused DoRA epilogue ----------------
  float* smf = (float*)hsm;
  float* st = smf;                  // t tile  [256][17]
  float* sw = smf + 256 * 17;       // W2s     [128*16]
  float* ss = sw + 128 * 16;        // scale-1 [128]
  for (int i = tid; i < 256 * 16; i += 256) st[(i >> 4) * 17 + (i & 15)] = g_t[(size_t)bM * 16 + i];
  for (int i = tid; i < 128 * 16; i += 256) sw[i] = g_W2s[(size_t)bN * 16 + i];
  if (tid < 128) ss[tid] = g_sm1[bN + tid];
  __syncthreads();

#pragma unroll
  for (int nt = 0; nt < 8; ++nt) {
    const int c = n_base + nt * 8 + 2 * (lane & 3);
    const float s0 = ss[c], s1 = ss[c + 1];
#pragma unroll
    for (int mt = 0; mt < 4; ++mt) {
      acc[mt][nt][0] *= s0; acc[mt][nt][1] *= s1;
      acc[mt][nt][2] *= s0; acc[mt][nt][3] *= s1;
    }
  }
#pragma unroll
  for (int r = 0; r < 16; ++r) {
    float tr[8], wr[16];
#pragma unroll
    for (int mt = 0; mt < 4; ++mt) {
      tr[mt * 2]     = st[(m_base + mt * 16 +     (lane >> 2)) * 17 + r];
      tr[mt * 2 + 1] = st[(m_base + mt * 16 + 8 + (lane >> 2)) * 17 + r];
    }
#pragma unroll
    for (int nt = 0; nt < 8; ++nt) {
      wr[nt * 2]     = sw[(n_base + nt * 8 + 2 * (lane & 3))     * 16 + r];
      wr[nt * 2 + 1] = sw[(n_base + nt * 8 + 2 * (lane & 3) + 1) * 16 + r];
    }
#pragma unroll
    for (int mt = 0; mt < 4; ++mt)
#pragma unroll
      for (int nt = 0; nt < 8; ++nt) {
        acc[mt][nt][0] += tr[mt * 2]     * wr[nt * 2];
        acc[mt][nt][1] += tr[mt * 2]     * wr[nt * 2 + 1];
        acc[mt][nt][2] += tr[mt * 2 + 1] * wr[nt * 2];
        acc[mt][nt][3] += tr[mt * 2 + 1] * wr[nt * 2 + 1];
      }
  }
#pragma unroll
  for (int mt = 0; mt < 4; ++mt)
#pragma unroll
    for (int h = 0; h < 2; ++h) {
      const int gm = bM + m_base + mt * 16 + h * 8 + (lane >> 2);
#pragma unroll
      for (int nt = 0; nt < 8; ++nt) {
        const int gn = bN + n_base + nt * 8 + 2 * (lane & 3);
        float2 v = make_float2(acc[mt][nt][h * 2], acc[mt][nt][h * 2 + 1]);
        *(float2*)(out + (size_t)gm * N_DIM + gn) = v;
      }
    }
}

// ============================================================
extern "C" void kernel_launch(void* const* d_in, const int* in_sizes, int n_in,
                              void* d_out, int out_size) {
  (void)in_sizes; (void)n_in; (void)out_size;
  const float* x   = (const float*)d_in[0];
  const float* U   = (const float*)d_in[1];
  const float* V   = (const float*)d_in[2];
  const float* S   = (const float*)d_in[3];
  const float* O   = (const float*)d_in[4];
  const float* mag = (const float*)d_in[5];
  const float* W   = (const float*)d_in[6];
  float* out = (float*)d_out;

  cudaFuncSetAttribute(k_gemm_h, cudaFuncAttributeMaxDynamicSharedMemorySize, GEMM_SMEM);

  const int n8x = (M_DIM * K_DIM) / 8;   // 8388608
  const int n8w = (N_DIM * K_DIM) / 8;   // 2097152
  k_split_h<0><<<n8x / 256, 256>>>(x, n8x);
  k_split_h<1><<<n8w / 256, 256>>>(W, n8w);
  k_prep<<<257, 256>>>(U, V, S, O);
  k_rowdot<0><<<N_DIM / 32, 256>>>(W, V);
  k_scale<<<N_DIM / 256, 256>>>(mag);
  k_rowdot<1><<<M_DIM / 32, 256>>>(x, V);
  k_gemm_h<<<dim3(N_DIM / BNt, M_DIM / BMt), 256, GEMM_SMEM>>>(out);
}

// round 4
// speedup vs baseline: 3.9055x; 2.1718x over previous
#include <cuda_runtime.h>
#include <cuda_fp16.h>
#include <cstdint>

#define M_DIM 16384
#define N_DIM 4096
#define K_DIM 4096
#define R_DIM 16

// ---- device scratch (module-load allocated; no runtime allocs) ----
__device__ float g_W2 [N_DIM * R_DIM];
__device__ float g_W2s[N_DIM * R_DIM];
__device__ float g_G  [R_DIM * R_DIM];
__device__ float g_d  [N_DIM * R_DIM];
__device__ float g_nb [N_DIM];
__device__ float g_t  [M_DIM * R_DIM];
__device__ float g_sm1[N_DIM];
// fp16 planes (hi only — plain fp16 GEMM, error budget allows it)
__device__ __half g_xh_h[(size_t)M_DIM * K_DIM];
__device__ __half g_wh_h[(size_t)N_DIM * K_DIM];

__device__ __forceinline__ uint32_t smem_u32(const void* p) {
  uint32_t a;
  asm("{ .reg .u64 t; cvta.to.shared.u64 t, %1; cvt.u32.u64 %0, t; }" : "=r"(a) : "l"(p));
  return a;
}
__device__ __forceinline__ void cpa16(uint32_t dst, const void* src) {
  asm volatile("cp.async.cg.shared.global [%0], [%1], 16;" :: "r"(dst), "l"(src) : "memory");
}

#define LDMX4(r, addr)                                                        \
  asm volatile("ldmatrix.sync.aligned.m8n8.x4.shared.b16 {%0,%1,%2,%3}, [%4];"\
               : "=r"((r)[0]), "=r"((r)[1]), "=r"((r)[2]), "=r"((r)[3])       \
               : "r"(addr))

#define MMA16816(d, a, b)                                                     \
  asm volatile("mma.sync.aligned.m16n8k16.row.col.f32.f16.f16.f32 "           \
               "{%0,%1,%2,%3}, {%4,%5,%6,%7}, {%8,%9}, {%0,%1,%2,%3};"        \
               : "+f"((d)[0]), "+f"((d)[1]), "+f"((d)[2]), "+f"((d)[3])       \
               : "r"((a)[0]), "r"((a)[1]), "r"((a)[2]), "r"((a)[3]),          \
                 "r"((b)[0]), "r"((b)[1]))

// ============================================================
// k_split_h: fp32 -> fp16 (rn), 8 elems/thread
// ============================================================
template <int WHICH>  // 0: x -> g_xh_h ; 1: W -> g_wh_h
__global__ void k_split_h(const float* __restrict__ in, int n8) {
  __half* hi = WHICH ? g_wh_h : g_xh_h;
  int i = blockIdx.x * blockDim.x + threadIdx.x;
  if (i >= n8) return;
  float4 v0 = ((const float4*)in)[2 * i];
  float4 v1 = ((const float4*)in)[2 * i + 1];
  union { __half h[8]; uint4 u; } H;
  H.h[0] = __float2half_rn(v0.x); H.h[1] = __float2half_rn(v0.y);
  H.h[2] = __float2half_rn(v0.z); H.h[3] = __float2half_rn(v0.w);
  H.h[4] = __float2half_rn(v1.x); H.h[5] = __float2half_rn(v1.y);
  H.h[6] = __float2half_rn(v1.z); H.h[7] = __float2half_rn(v1.w);
  ((uint4*)hi)[i] = H.u;
}

// ============================================================
// small prep kernels
// ============================================================
__global__ void k_prep(const float* __restrict__ U, const float* __restrict__ V,
                       const float* __restrict__ S, const float* __restrict__ O) {
  if (blockIdx.x < 256) {
    int idx = blockIdx.x * 256 + threadIdx.x;
    int o = idx >> 4, r = idx & 15;
    g_W2[idx] = O[o] * U[idx] * S[r];
  } else {
    int r  = threadIdx.x >> 4;
    int r2 = threadIdx.x & 15;
    const float4* va = (const float4*)(V + r  * K_DIM);
    const float4* vb = (const float4*)(V + r2 * K_DIM);
    float s = 0.f;
    for (int i = 0; i < K_DIM / 4; ++i) {
      float4 a = va[i], b = vb[i];
      s += a.x * b.x + a.y * b.y + a.z * b.z + a.w * b.w;
    }
    g_G[threadIdx.x] = s;
  }
}

// rowdot with float4 gmem loads (latency-bound fix)
template <int MODE>
__global__ void k_rowdot(const float* __restrict__ in, const float* __restrict__ V) {
  __shared__ float vs[R_DIM * 512];
  const int tid = threadIdx.x, lane = tid & 31, warp = tid >> 5;
  const int m0 = blockIdx.x * 32 + warp * 4;
  float acc[4][16];
  float nacc[4] = {0.f, 0.f, 0.f, 0.f};
#pragma unroll
  for (int m = 0; m < 4; ++m)
#pragma unroll
    for (int r = 0; r < 16; ++r) acc[m][r] = 0.f;

  for (int kc = 0; kc < K_DIM; kc += 512) {
    __syncthreads();
    for (int i = tid; i < R_DIM * 128; i += 256) {
      int r = i >> 7, c4 = (i & 127) << 2;
      *(float4*)&vs[r * 512 + c4] = *(const float4*)&V[r * K_DIM + kc + c4];
    }
    __syncthreads();
#pragma unroll 2
    for (int i = lane; i < 128; i += 32) {
      float4 xv[4];
#pragma unroll
      for (int m = 0; m < 4; ++m)
        xv[m] = *(const float4*)&in[(size_t)(m0 + m) * K_DIM + kc + i * 4];
      if (MODE == 0) {
#pragma unroll
        for (int m = 0; m < 4; ++m)
          nacc[m] += xv[m].x * xv[m].x + xv[m].y * xv[m].y +
                     xv[m].z * xv[m].z + xv[m].w * xv[m].w;
      }
#pragma unroll
      for (int r = 0; r < 16; ++r) {
        float4 vv = *(const float4*)&vs[r * 512 + i * 4];
#pragma unroll
        for (int m = 0; m < 4; ++m)
          acc[m][r] += xv[m].x * vv.x + xv[m].y * vv.y +
                       xv[m].z * vv.z + xv[m].w * vv.w;
      }
    }
  }
#pragma unroll
  for (int m = 0; m < 4; ++m) {
#pragma unroll
    for (int r = 0; r < 16; ++r) {
      float v = acc[m][r];
#pragma unroll
      for (int off = 16; off; off >>= 1) v += __shfl_xor_sync(0xffffffffu, v, off);
      acc[m][r] = v;
    }
    if (MODE == 0) {
      float v = nacc[m];
#pragma unroll
      for (int off = 16; off; off >>= 1) v += __shfl_xor_sync(0xffffffffu, v, off);
      nacc[m] = v;
    }
  }
  if (lane == 0) {
    float* dout = (MODE == 0) ? g_d : g_t;
#pragma unroll
    for (int m = 0; m < 4; ++m) {
#pragma unroll
      for (int r = 0; r < 16; ++r) dout[(m0 + m) * 16 + r] = acc[m][r];
      if (MODE == 0) g_nb[m0 + m] = nacc[m];
    }
  }
}

__global__ void k_scale(const float* __restrict__ mag) {
  int o = blockIdx.x * 256 + threadIdx.x;
  float w2[16];
#pragma unroll
  for (int r = 0; r < 16; ++r) w2[r] = g_W2[o * 16 + r];
  float n2 = g_nb[o];
#pragma unroll
  for (int r = 0; r < 16; ++r) n2 += 2.f * w2[r] * g_d[o * 16 + r];
#pragma unroll
  for (int r = 0; r < 16; ++r) {
    float gr = 0.f;
#pragma unroll
    for (int r2 = 0; r2 < 16; ++r2) gr += g_G[r * 16 + r2] * w2[r2];
    n2 += w2[r] * gr;
  }
  float sc = mag[o] / sqrtf(n2);
  g_sm1[o] = sc - 1.f;
#pragma unroll
  for (int r = 0; r < 16; ++r) g_W2s[o * 16 + r] = sc * w2[r];
}

// ============================================================
// k_gemm_h: plain fp16 mma.sync m16n8k16, fp32 accum.
// BM=256 BN=128 BK=64, 4-stage cp.async, fused DoRA epilogue.
// ============================================================
#define BMt 256
#define BNt 128
#define BKh 64
#define NKT (K_DIM / BKh)            // 64
#define LSTR 72                      // halfs per smem row (144B)
#define A_PLANE_H (256 * LSTR)       // 18432 halfs
#define B_PLANE_H (128 * LSTR)       // 9216  halfs
#define STAGE_H (A_PLANE_H + B_PLANE_H)    // 27648 halfs = 55296 B
#define NSTG 4
#define GEMM_SMEM (NSTG * STAGE_H * 2)     // 221184 bytes

__global__ void __launch_bounds__(256, 1) k_gemm_h(float* __restrict__ out) {
  extern __shared__ __align__(16) __half hsm[];
  const int tid  = threadIdx.x;
  const int lane = tid & 31;
  const int warp = tid >> 5;
  const int m_base = (warp >> 1) * 64;   // 4 warps over M
  const int n_base = (warp & 1) * 64;    // 2 warps over N
  const int bM = blockIdx.y * BMt;
  const int bN = blockIdx.x * BNt;
  const uint32_t smb = smem_u32(hsm);

  float acc[4][8][4];
#pragma unroll
  for (int i = 0; i < 4; ++i)
#pragma unroll
    for (int j = 0; j < 8; ++j)
#pragma unroll
      for (int e = 0; e < 4; ++e) acc[i][j][e] = 0.f;

  auto load_stage = [&](int s, int kt) {
    const int k0 = kt * BKh;
    const uint32_t base = smb + (uint32_t)s * STAGE_H * 2;
#pragma unroll
    for (int ci = 0; ci < 12; ++ci) {
      const int c = ci * 256 + tid;          // 0..3071
      const __half* src;
      uint32_t dst;
      if (c < 2048) {                         // A hi
        const int row = c >> 3, q = c & 7;
        src = g_xh_h + (size_t)(bM + row) * K_DIM + k0 + q * 8;
        dst = base + (uint32_t)(row * LSTR + q * 8) * 2;
      } else {                                // B hi
        const int cb = c - 2048, row = cb >> 3, q = cb & 7;
        src = g_wh_h + (size_t)(bN + row) * K_DIM + k0 + q * 8;
        dst = base + (uint32_t)(A_PLANE_H + row * LSTR + q * 8) * 2;
      }
      cpa16(dst, src);
    }
  };

#pragma unroll
  for (int s = 0; s < 3; ++s) {
    load_stage(s, s);
    asm volatile("cp.async.commit_group;" ::: "memory");
  }

  const int arow = (lane & 15);
  const int acol = (lane >> 4) << 3;
  const int brow = (lane & 7) + ((lane >> 4) << 3);
  const int bcol = ((lane >> 3) & 1) << 3;

  for (int kt = 0; kt < NKT; ++kt) {
    if (kt + 3 < NKT) load_stage((kt + 3) & 3, kt + 3);
    asm volatile("cp.async.commit_group;" ::: "memory");
    asm volatile("cp.async.wait_group 3;" ::: "memory");
    __syncthreads();

    const uint32_t sbase = smb + (uint32_t)(kt & 3) * STAGE_H * 2;
    const uint32_t aB = sbase;
    const uint32_t bB = sbase + A_PLANE_H * 2;

#pragma unroll
    for (int kk = 0; kk < 4; ++kk) {
      const int kof = kk * 16;
      uint32_t ah[4][4], bh[8][2];
#pragma unroll
      for (int mt = 0; mt < 4; ++mt) {
        const uint32_t off = (uint32_t)((m_base + mt * 16 + arow) * LSTR + kof + acol) * 2;
        LDMX4(ah[mt], aB + off);
      }
#pragma unroll
      for (int p = 0; p < 4; ++p) {
        const uint32_t off = (uint32_t)((n_base + p * 16 + brow) * LSTR + kof + bcol) * 2;
        uint32_t r[4];
        LDMX4(r, bB + off);
        bh[2 * p][0] = r[0]; bh[2 * p][1] = r[1];
        bh[2 * p + 1][0] = r[2]; bh[2 * p + 1][1] = r[3];
      }
#pragma unroll
      for (int mt = 0; mt < 4; ++mt)
#pragma unroll
        for (int nt = 0; nt < 8; ++nt)
          MMA16816(acc[mt][nt], ah[mt], bh[nt]);
    }
    __syncthreads();
  }

  // ---------------- fused DoRA epilogue ----------------
  float* smf = (float*)hsm;
  float* st = smf;                  // t tile  [256][17]
  float* sw = smf + 256 * 17;       // W2s     [128*16]
  float* ss = sw + 128 * 16;        // scale-1 [128]
  for (int i = tid; i < 256 * 16; i += 256) st[(i >> 4) * 17 + (i & 15)] = g_t[(size_t)bM * 16 + i];
  for (int i = tid; i < 128 * 16; i += 256) sw[i] = g_W2s[(size_t)bN * 16 + i];
  if (tid < 128) ss[tid] = g_sm1[bN + tid];
  __syncthreads();

#pragma unroll
  for (int nt = 0; nt < 8; ++nt) {
    const int c = n_base + nt * 8 + 2 * (lane & 3);
    const float s0 = ss[c], s1 = ss[c + 1];
#pragma unroll
    for (int mt = 0; mt < 4; ++mt) {
      acc[mt][nt][0] *= s0; acc[mt][nt][1] *= s1;
      acc[mt][nt][2] *= s0; acc[mt][nt][3] *= s1;
    }
  }
#pragma unroll
  for (int r = 0; r < 16; ++r) {
    float tr[8], wr[16];
#pragma unroll
    for (int mt = 0; mt < 4; ++mt) {
      tr[mt * 2]     = st[(m_base + mt * 16 +     (lane >> 2)) * 17 + r];
      tr[mt * 2 + 1] = st[(m_base + mt * 16 + 8 + (lane >> 2)) * 17 + r];
    }
#pragma unroll
    for (int nt = 0; nt < 8; ++nt) {
      wr[nt * 2]     = sw[(n_base + nt * 8 + 2 * (lane & 3))     * 16 + r];
      wr[nt * 2 + 1] = sw[(n_base + nt * 8 + 2 * (lane & 3) + 1) * 16 + r];
    }
#pragma unroll
    for (int mt = 0; mt < 4; ++mt)
#pragma unroll
      for (int nt = 0; nt < 8; ++nt) {
        acc[mt][nt][0] += tr[mt * 2]     * wr[nt * 2];
        acc[mt][nt][1] += tr[mt * 2]     * wr[nt * 2 + 1];
        acc[mt][nt][2] += tr[mt * 2 + 1] * wr[nt * 2];
        acc[mt][nt][3] += tr[mt * 2 + 1] * wr[nt * 2 + 1];
      }
  }
#pragma unroll
  for (int mt = 0; mt < 4; ++mt)
#pragma unroll
    for (int h = 0; h < 2; ++h) {
      const int gm = bM + m_base + mt * 16 + h * 8 + (lane >> 2);
#pragma unroll
      for (int nt = 0; nt < 8; ++nt) {
        const int gn = bN + n_base + nt * 8 + 2 * (lane & 3);
        float2 v = make_float2(acc[mt][nt][h * 2], acc[mt][nt][h * 2 + 1]);
        *(float2*)(out + (size_t)gm * N_DIM + gn) = v;
      }
    }
}

// ============================================================
extern "C" void kernel_launch(void* const* d_in, const int* in_sizes, int n_in,
                              void* d_out, int out_size) {
  (void)in_sizes; (void)n_in; (void)out_size;
  const float* x   = (const float*)d_in[0];
  const float* U   = (const float*)d_in[1];
  const float* V   = (const float*)d_in[2];
  const float* S   = (const float*)d_in[3];
  const float* O   = (const float*)d_in[4];
  const float* mag = (const float*)d_in[5];
  const float* W   = (const float*)d_in[6];
  float* out = (float*)d_out;

  cudaFuncSetAttribute(k_gemm_h, cudaFuncAttributeMaxDynamicSharedMemorySize, GEMM_SMEM);

  const int n8x = (M_DIM * K_DIM) / 8;   // 8388608
  const int n8w = (N_DIM * K_DIM) / 8;   // 2097152
  k_split_h<0><<<n8x / 256, 256>>>(x, n8x);
  k_split_h<1><<<n8w / 256, 256>>>(W, n8w);
  k_prep<<<257, 256>>>(U, V, S, O);
  k_rowdot<0><<<N_DIM / 32, 256>>>(W, V);
  k_scale<<<N_DIM / 256, 256>>>(mag);
  k_rowdot<1><<<M_DIM / 32, 256>>>(x, V);
  k_gemm_h<<<dim3(N_DIM / BNt, M_DIM / BMt), 256, GEMM_SMEM>>>(out);
}

// round 5
// speedup vs baseline: 4.5268x; 1.1591x over previous
#include <cuda_runtime.h>
#include <cuda_fp16.h>
#include <cstdint>

#define M_DIM 16384
#define N_DIM 4096
#define K_DIM 4096
#define R_DIM 16

// ---- device scratch (module-load allocated; no runtime allocs) ----
__device__ float g_W2 [N_DIM * R_DIM];
__device__ float g_W2s[N_DIM * R_DIM];
__device__ float g_G  [R_DIM * R_DIM];
__device__ float g_d  [N_DIM * R_DIM];
__device__ float g_nb [N_DIM];
__device__ float g_t  [M_DIM * R_DIM];
__device__ float g_sm1[N_DIM];
__device__ __half g_xh_h[(size_t)M_DIM * K_DIM];
__device__ __half g_wh_h[(size_t)N_DIM * K_DIM];
__device__ __half g_vh  [R_DIM * K_DIM];

__device__ __forceinline__ uint32_t smem_u32(const void* p) {
  uint32_t a;
  asm("{ .reg .u64 t; cvta.to.shared.u64 t, %1; cvt.u32.u64 %0, t; }" : "=r"(a) : "l"(p));
  return a;
}
__device__ __forceinline__ void cpa16(uint32_t dst, const void* src) {
  asm volatile("cp.async.cg.shared.global [%0], [%1], 16;" :: "r"(dst), "l"(src) : "memory");
}

#define LDMX4(r, addr)                                                        \
  asm volatile("ldmatrix.sync.aligned.m8n8.x4.shared.b16 {%0,%1,%2,%3}, [%4];"\
               : "=r"((r)[0]), "=r"((r)[1]), "=r"((r)[2]), "=r"((r)[3])       \
               : "r"(addr))

#define MMA16816(d, a, b)                                                     \
  asm volatile("mma.sync.aligned.m16n8k16.row.col.f32.f16.f16.f32 "           \
               "{%0,%1,%2,%3}, {%4,%5,%6,%7}, {%8,%9}, {%0,%1,%2,%3};"        \
               : "+f"((d)[0]), "+f"((d)[1]), "+f"((d)[2]), "+f"((d)[3])       \
               : "r"((a)[0]), "r"((a)[1]), "r"((a)[2]), "r"((a)[3]),          \
                 "r"((b)[0]), "r"((b)[1]))

// ============================================================
// k_split_x: x fp32 -> fp16, element-parallel (memory-bound)
// ============================================================
__global__ void k_split_x(const float* __restrict__ in, int n8) {
  int i = blockIdx.x * blockDim.x + threadIdx.x;
  if (i >= n8) return;
  float4 v0 = ((const float4*)in)[2 * i];
  float4 v1 = ((const float4*)in)[2 * i + 1];
  union { __half2 h[4]; uint4 u; } H;
  H.h[0] = __floats2half2_rn(v0.x, v0.y);
  H.h[1] = __floats2half2_rn(v0.z, v0.w);
  H.h[2] = __floats2half2_rn(v1.x, v1.y);
  H.h[3] = __floats2half2_rn(v1.z, v1.w);
  ((uint4*)g_xh_h)[i] = H.u;
}

// ============================================================
// k_split_w_nb: W fp32 -> fp16 + per-row ||W||^2 (warp per row)
// ============================================================
__global__ void k_split_w_nb(const float* __restrict__ W) {
  const int lane = threadIdx.x & 31, warp = threadIdx.x >> 5;
  const int row = blockIdx.x * 8 + warp;
  const float* src = W + (size_t)row * K_DIM;
  __half* dst = g_wh_h + (size_t)row * K_DIM;
  float nacc = 0.f;
#pragma unroll 8
  for (int i = 0; i < 32; ++i) {
    float4 v = *(const float4*)(src + i * 128 + lane * 4);
    nacc += v.x * v.x + v.y * v.y + v.z * v.z + v.w * v.w;
    union { __half2 h[2]; uint2 u; } P;
    P.h[0] = __floats2half2_rn(v.x, v.y);
    P.h[1] = __floats2half2_rn(v.z, v.w);
    *(uint2*)(dst + i * 128 + lane * 4) = P.u;
  }
#pragma unroll
  for (int off = 16; off; off >>= 1) nacc += __shfl_xor_sync(0xffffffffu, nacc, off);
  if (lane == 0) g_nb[row] = nacc;
}

// ============================================================
// k_prep: blocks 0-255: W2 = O*U*S ; 256-511: G = V V^T (block/pair);
//         512-519: V -> fp16
// ============================================================
__global__ void k_prep(const float* __restrict__ U, const float* __restrict__ V,
                       const float* __restrict__ S, const float* __restrict__ O) {
  const int b = blockIdx.x, tid = threadIdx.x;
  if (b < 256) {
    int idx = b * 256 + tid;
    int o = idx >> 4, r = idx & 15;
    g_W2[idx] = O[o] * U[idx] * S[r];
  } else if (b < 512) {
    const int p = b - 256, r = p >> 4, r2 = p & 15;
    const float4* va = (const float4*)(V + r  * K_DIM);
    const float4* vb = (const float4*)(V + r2 * K_DIM);
    float s = 0.f;
    for (int i = tid; i < 1024; i += 256) {
      float4 a = va[i], c = vb[i];
      s += a.x * c.x + a.y * c.y + a.z * c.z + a.w * c.w;
    }
    __shared__ float red[256];
    red[tid] = s; __syncthreads();
#pragma unroll
    for (int st = 128; st; st >>= 1) {
      if (tid < st) red[tid] += red[tid + st];
      __syncthreads();
    }
    if (tid == 0) g_G[p] = red[0];
  } else {
#pragma unroll
    for (int j = 0; j < 8; ++j) {
      int idx = (b - 512) * 8192 + j * 1024 + tid * 4;
      float4 v = *(const float4*)(V + idx);
      union { __half2 h[2]; uint2 u; } P;
      P.h[0] = __floats2half2_rn(v.x, v.y);
      P.h[1] = __floats2half2_rn(v.z, v.w);
      *(uint2*)(g_vh + idx) = P.u;
    }
  }
}

// ============================================================
// k_t: tensor-core skinny GEMM: t = xh @ Vh^T (blocks 0..127)
//                               d = wh @ Vh^T (blocks 128..159)
// block = 256 thr (8 warps), 128 rows/block, warp = 16 rows.
// ============================================================
__global__ void __launch_bounds__(256) k_t() {
  __shared__ __align__(16) __half As[2][128 * 72];
  __shared__ __align__(16) __half Vs[2][16 * 72];
  const int tid = threadIdx.x, lane = tid & 31, warp = tid >> 5;
  const bool isw = blockIdx.x >= 128;
  const int row0 = (isw ? (int)blockIdx.x - 128 : (int)blockIdx.x) * 128;
  const __half* A = isw ? g_wh_h : g_xh_h;
  float* outp = isw ? g_d : g_t;

  auto load = [&](int s, int kc) {
    const int k0 = kc * 64;
    const uint32_t ab = smem_u32(&As[s][0]);
#pragma unroll
    for (int i = 0; i < 4; ++i) {
      int c = i * 256 + tid, r = c >> 3, q = c & 7;
      cpa16(ab + (uint32_t)(r * 72 + q * 8) * 2,
            A + (size_t)(row0 + r) * K_DIM + k0 + q * 8);
    }
    if (tid < 128) {
      int r = tid >> 3, q = tid & 7;
      cpa16(smem_u32(&Vs[s][0]) + (uint32_t)(r * 72 + q * 8) * 2,
            g_vh + r * K_DIM + k0 + q * 8);
    }
  };

  float acc[2][4];
#pragma unroll
  for (int i = 0; i < 2; ++i)
#pragma unroll
    for (int e = 0; e < 4; ++e) acc[i][e] = 0.f;

  load(0, 0);
  asm volatile("cp.async.commit_group;" ::: "memory");

  const int arow = lane & 15, acol = (lane >> 4) << 3;
  const int brow = (lane & 7) + ((lane >> 4) << 3), bcol = ((lane >> 3) & 1) << 3;

  for (int kc = 0; kc < 64; ++kc) {
    if (kc + 1 < 64) load((kc + 1) & 1, kc + 1);
    asm volatile("cp.async.commit_group;" ::: "memory");
    asm volatile("cp.async.wait_group 1;" ::: "memory");
    __syncthreads();
    const uint32_t aB = smem_u32(&As[kc & 1][0]);
    const uint32_t bB = smem_u32(&Vs[kc & 1][0]);
#pragma unroll
    for (int kk = 0; kk < 4; ++kk) {
      uint32_t a[4], bt[4];
      LDMX4(a, aB + (uint32_t)((warp * 16 + arow) * 72 + kk * 16 + acol) * 2);
      LDMX4(bt, bB + (uint32_t)(brow * 72 + kk * 16 + bcol) * 2);
      uint32_t b0[2] = {bt[0], bt[1]}, b1[2] = {bt[2], bt[3]};
      MMA16816(acc[0], a, b0);
      MMA16816(acc[1], a, b1);
    }
    __syncthreads();
  }

  const int r1 = row0 + warp * 16 + (lane >> 2);
#pragma unroll
  for (int nt = 0; nt < 2; ++nt) {
    const int c = nt * 8 + 2 * (lane & 3);
    *(float2*)&outp[(size_t)r1 * 16 + c]       = make_float2(acc[nt][0], acc[nt][1]);
    *(float2*)&outp[(size_t)(r1 + 8) * 16 + c] = make_float2(acc[nt][2], acc[nt][3]);
  }
}

// ============================================================
// k_scale
// ============================================================
__global__ void k_scale(const float* __restrict__ mag) {
  int o = blockIdx.x * 256 + threadIdx.x;
  float w2[16];
#pragma unroll
  for (int r = 0; r < 16; ++r) w2[r] = g_W2[o * 16 + r];
  float n2 = g_nb[o];
#pragma unroll
  for (int r = 0; r < 16; ++r) n2 += 2.f * w2[r] * g_d[o * 16 + r];
#pragma unroll
  for (int r = 0; r < 16; ++r) {
    float gr = 0.f;
#pragma unroll
    for (int r2 = 0; r2 < 16; ++r2) gr += g_G[r * 16 + r2] * w2[r2];
    n2 += w2[r] * gr;
  }
  float sc = mag[o] / sqrtf(n2);
  g_sm1[o] = sc - 1.f;
#pragma unroll
  for (int r = 0; r < 16; ++r) g_W2s[o * 16 + r] = sc * w2[r];
}

// ============================================================
// k_gemm_h: unchanged from R4 (at legacy HMMA ceiling, ~99%)
// ============================================================
#define BMt 256
#define BNt 128
#define BKh 64
#define NKT (K_DIM / BKh)
#define LSTR 72
#define A_PLANE_H (256 * LSTR)
#define B_PLANE_H (128 * LSTR)
#define STAGE_H (A_PLANE_H + B_PLANE_H)
#define NSTG 4
#define GEMM_SMEM (NSTG * STAGE_H * 2)

__global__ void __launch_bounds__(256, 1) k_gemm_h(float* __restrict__ out) {
  extern __shared__ __align__(16) __half hsm[];
  const int tid  = threadIdx.x;
  const int lane = tid & 31;
  const int warp = tid >> 5;
  const int m_base = (warp >> 1) * 64;
  const int n_base = (warp & 1) * 64;
  const int bM = blockIdx.y * BMt;
  const int bN = blockIdx.x * BNt;
  const uint32_t smb = smem_u32(hsm);

  float acc[4][8][4];
#pragma unroll
  for (int i = 0; i < 4; ++i)
#pragma unroll
    for (int j = 0; j < 8; ++j)
#pragma unroll
      for (int e = 0; e < 4; ++e) acc[i][j][e] = 0.f;

  auto load_stage = [&](int s, int kt) {
    const int k0 = kt * BKh;
    const uint32_t base = smb + (uint32_t)s * STAGE_H * 2;
#pragma unroll
    for (int ci = 0; ci < 12; ++ci) {
      const int c = ci * 256 + tid;
      const __half* src;
      uint32_t dst;
      if (c < 2048) {
        const int row = c >> 3, q = c & 7;
        src = g_xh_h + (size_t)(bM + row) * K_DIM + k0 + q * 8;
        dst = base + (uint32_t)(row * LSTR + q * 8) * 2;
      } else {
        const int cb = c - 2048, row = cb >> 3, q = cb & 7;
        src = g_wh_h + (size_t)(bN + row) * K_DIM + k0 + q * 8;
        dst = base + (uint32_t)(A_PLANE_H + row * LSTR + q * 8) * 2;
      }
      cpa16(dst, src);
    }
  };

#pragma unroll
  for (int s = 0; s < 3; ++s) {
    load_stage(s, s);
    asm volatile("cp.async.commit_group;" ::: "memory");
  }

  const int arow = (lane & 15);
  const int acol = (lane >> 4) << 3;
  const int brow = (lane & 7) + ((lane >> 4) << 3);
  const int bcol = ((lane >> 3) & 1) << 3;

  for (int kt = 0; kt < NKT; ++kt) {
    if (kt + 3 < NKT) load_stage((kt + 3) & 3, kt + 3);
    asm volatile("cp.async.commit_group;" ::: "memory");
    asm volatile("cp.async.wait_group 3;" ::: "memory");
    __syncthreads();

    const uint32_t sbase = smb + (uint32_t)(kt & 3) * STAGE_H * 2;
    const uint32_t aB = sbase;
    const uint32_t bB = sbase + A_PLANE_H * 2;

#pragma unroll
    for (int kk = 0; kk < 4; ++kk) {
      const int kof = kk * 16;
      uint32_t ah[4][4], bh[8][2];
#pragma unroll
      for (int mt = 0; mt < 4; ++mt) {
        const uint32_t off = (uint32_t)((m_base + mt * 16 + arow) * LSTR + kof + acol) * 2;
        LDMX4(ah[mt], aB + off);
      }
#pragma unroll
      for (int p = 0; p < 4; ++p) {
        const uint32_t off = (uint32_t)((n_base + p * 16 + brow) * LSTR + kof + bcol) * 2;
        uint32_t r[4];
        LDMX4(r, bB + off);
        bh[2 * p][0] = r[0]; bh[2 * p][1] = r[1];
        bh[2 * p + 1][0] = r[2]; bh[2 * p + 1][1] = r[3];
      }
#pragma unroll
      for (int mt = 0; mt < 4; ++mt)
#pragma unroll
        for (int nt = 0; nt < 8; ++nt)
          MMA16816(acc[mt][nt], ah[mt], bh[nt]);
    }
    __syncthreads();
  }

  // fused DoRA epilogue
  float* smf = (float*)hsm;
  float* st = smf;
  float* sw = smf + 256 * 17;
  float* ss = sw + 128 * 16;
  for (int i = tid; i < 256 * 16; i += 256) st[(i >> 4) * 17 + (i & 15)] = g_t[(size_t)bM * 16 + i];
  for (int i = tid; i < 128 * 16; i += 256) sw[i] = g_W2s[(size_t)bN * 16 + i];
  if (tid < 128) ss[tid] = g_sm1[bN + tid];
  __syncthreads();

#pragma unroll
  for (int nt = 0; nt < 8; ++nt) {
    const int c = n_base + nt * 8 + 2 * (lane & 3);
    const float s0 = ss[c], s1 = ss[c + 1];
#pragma unroll
    for (int mt = 0; mt < 4; ++mt) {
      acc[mt][nt][0] *= s0; acc[mt][nt][1] *= s1;
      acc[mt][nt][2] *= s0; acc[mt][nt][3] *= s1;
    }
  }
#pragma unroll
  for (int r = 0; r < 16; ++r) {
    float tr[8], wr[16];
#pragma unroll
    for (int mt = 0; mt < 4; ++mt) {
      tr[mt * 2]     = st[(m_base + mt * 16 +     (lane >> 2)) * 17 + r];
      tr[mt * 2 + 1] = st[(m_base + mt * 16 + 8 + (lane >> 2)) * 17 + r];
    }
#pragma unroll
    for (int nt = 0; nt < 8; ++nt) {
      wr[nt * 2]     = sw[(n_base + nt * 8 + 2 * (lane & 3))     * 16 + r];
      wr[nt * 2 + 1] = sw[(n_base + nt * 8 + 2 * (lane & 3) + 1) * 16 + r];
    }
#pragma unroll
    for (int mt = 0; mt < 4; ++mt)
#pragma unroll
      for (int nt = 0; nt < 8; ++nt) {
        acc[mt][nt][0] += tr[mt * 2]     * wr[nt * 2];
        acc[mt][nt][1] += tr[mt * 2]     * wr[nt * 2 + 1];
        acc[mt][nt][2] += tr[mt * 2 + 1] * wr[nt * 2];
        acc[mt][nt][3] += tr[mt * 2 + 1] * wr[nt * 2 + 1];
      }
  }
#pragma unroll
  for (int mt = 0; mt < 4; ++mt)
#pragma unroll
    for (int h = 0; h < 2; ++h) {
      const int gm = bM + m_base + mt * 16 + h * 8 + (lane >> 2);
#pragma unroll
      for (int nt = 0; nt < 8; ++nt) {
        const int gn = bN + n_base + nt * 8 + 2 * (lane & 3);
        float2 v = make_float2(acc[mt][nt][h * 2], acc[mt][nt][h * 2 + 1]);
        *(float2*)(out + (size_t)gm * N_DIM + gn) = v;
      }
    }
}

// ============================================================
extern "C" void kernel_launch(void* const* d_in, const int* in_sizes, int n_in,
                              void* d_out, int out_size) {
  (void)in_sizes; (void)n_in; (void)out_size;
  const float* x   = (const float*)d_in[0];
  const float* U   = (const float*)d_in[1];
  const float* V   = (const float*)d_in[2];
  const float* S   = (const float*)d_in[3];
  const float* O   = (const float*)d_in[4];
  const float* mag = (const float*)d_in[5];
  const float* W   = (const float*)d_in[6];
  float* out = (float*)d_out;

  cudaFuncSetAttribute(k_gemm_h, cudaFuncAttributeMaxDynamicSharedMemorySize, GEMM_SMEM);

  const int n8x = (M_DIM * K_DIM) / 8;
  k_split_x<<<n8x / 256, 256>>>(x, n8x);          // 1
  k_split_w_nb<<<N_DIM / 8, 256>>>(W);            // 2
  k_prep<<<520, 256>>>(U, V, S, O);               // 3
  k_t<<<160, 256>>>();                            // 4
  k_scale<<<N_DIM / 256, 256>>>(mag);             // 5
  k_gemm_h<<<dim3(N_DIM / BNt, M_DIM / BMt), 256, GEMM_SMEM>>>(out);  // 6 (ncu target)
}

// round 6
// speedup vs baseline: 6.1551x; 1.3597x over previous
#include <cuda_runtime.h>
#include <cuda.h>
#include <cuda_fp16.h>
#include <cstdint>

#define M_DIM 16384
#define N_DIM 4096
#define K_DIM 4096
#define R_DIM 16

// ---- device scratch (module-load allocated; no runtime allocs) ----
__device__ float g_W2 [N_DIM * R_DIM];
__device__ float g_W2s[N_DIM * R_DIM];
__device__ float g_G  [R_DIM * R_DIM];
__device__ float g_d  [N_DIM * R_DIM];
__device__ float g_nb [N_DIM];
__device__ float g_t  [M_DIM * R_DIM];
__device__ float g_sm1[N_DIM];
__device__ __half g_xh_h[(size_t)M_DIM * K_DIM];
__device__ __half g_wh_h[(size_t)N_DIM * K_DIM];
__device__ __half g_vh  [R_DIM * K_DIM];

__device__ __forceinline__ uint32_t smem_u32(const void* p) {
  uint32_t a;
  asm("{ .reg .u64 t; cvta.to.shared.u64 t, %1; cvt.u32.u64 %0, t; }" : "=r"(a) : "l"(p));
  return a;
}
__device__ __forceinline__ void cpa16(uint32_t dst, const void* src) {
  asm volatile("cp.async.cg.shared.global [%0], [%1], 16;" :: "r"(dst), "l"(src) : "memory");
}
__device__ __forceinline__ void bar_init(uint32_t a, uint32_t cnt) {
  asm volatile("mbarrier.init.shared.b64 [%0], %1;" :: "r"(a), "r"(cnt) : "memory");
}
__device__ __forceinline__ void bar_arrive(uint32_t a) {
  asm volatile("mbarrier.arrive.shared.b64 _, [%0];" :: "r"(a) : "memory");
}
__device__ __forceinline__ void bar_expect_tx(uint32_t a, uint32_t tx) {
  asm volatile("mbarrier.arrive.expect_tx.shared.b64 _, [%0], %1;" :: "r"(a), "r"(tx) : "memory");
}
__device__ __forceinline__ void bar_wait(uint32_t a, uint32_t parity) {
  asm volatile(
    "{\n\t.reg .pred P;\n\t"
    "BW_%=:\n\t"
    "mbarrier.try_wait.parity.shared.b64 P, [%0], %1, 0x989680;\n\t"
    "@!P bra BW_%=;\n\t}"
    :: "r"(a), "r"(parity) : "memory");
}
__device__ __forceinline__ void tma2d(uint32_t dst, const void* map, int cx, int cy, uint32_t bar) {
  asm volatile(
    "cp.async.bulk.tensor.2d.shared::cluster.global.tile.mbarrier::complete_tx::bytes "
    "[%0], [%1, {%2, %3}], [%4];"
    :: "r"(dst), "l"(map), "r"(cx), "r"(cy), "r"(bar) : "memory");
}

#define SWZ(o) ((o) ^ (((o) >> 3) & 0x70))

#define LDMX4(r, addr)                                                        \
  asm volatile("ldmatrix.sync.aligned.m8n8.x4.shared.b16 {%0,%1,%2,%3}, [%4];"\
               : "=r"((r)[0]), "=r"((r)[1]), "=r"((r)[2]), "=r"((r)[3])       \
               : "r"(addr))

#define MMA16816(d, a, b)                                                     \
  asm volatile("mma.sync.aligned.m16n8k16.row.col.f32.f16.f16.f32 "           \
               "{%0,%1,%2,%3}, {%4,%5,%6,%7}, {%8,%9}, {%0,%1,%2,%3};"        \
               : "+f"((d)[0]), "+f"((d)[1]), "+f"((d)[2]), "+f"((d)[3])       \
               : "r"((a)[0]), "r"((a)[1]), "r"((a)[2]), "r"((a)[3]),          \
                 "r"((b)[0]), "r"((b)[1]))

// ============================================================
// prep kernels (unchanged from R5)
// ============================================================
__global__ void k_split_x(const float* __restrict__ in, int n8) {
  int i = blockIdx.x * blockDim.x + threadIdx.x;
  if (i >= n8) return;
  float4 v0 = ((const float4*)in)[2 * i];
  float4 v1 = ((const float4*)in)[2 * i + 1];
  union { __half2 h[4]; uint4 u; } H;
  H.h[0] = __floats2half2_rn(v0.x, v0.y);
  H.h[1] = __floats2half2_rn(v0.z, v0.w);
  H.h[2] = __floats2half2_rn(v1.x, v1.y);
  H.h[3] = __floats2half2_rn(v1.z, v1.w);
  ((uint4*)g_xh_h)[i] = H.u;
}

__global__ void k_split_w_nb(const float* __restrict__ W) {
  const int lane = threadIdx.x & 31, warp = threadIdx.x >> 5;
  const int row = blockIdx.x * 8 + warp;
  const float* src = W + (size_t)row * K_DIM;
  __half* dst = g_wh_h + (size_t)row * K_DIM;
  float nacc = 0.f;
#pragma unroll 8
  for (int i = 0; i < 32; ++i) {
    float4 v = *(const float4*)(src + i * 128 + lane * 4);
    nacc += v.x * v.x + v.y * v.y + v.z * v.z + v.w * v.w;
    union { __half2 h[2]; uint2 u; } P;
    P.h[0] = __floats2half2_rn(v.x, v.y);
    P.h[1] = __floats2half2_rn(v.z, v.w);
    *(uint2*)(dst + i * 128 + lane * 4) = P.u;
  }
#pragma unroll
  for (int off = 16; off; off >>= 1) nacc += __shfl_xor_sync(0xffffffffu, nacc, off);
  if (lane == 0) g_nb[row] = nacc;
}

__global__ void k_prep(const float* __restrict__ U, const float* __restrict__ V,
                       const float* __restrict__ S, const float* __restrict__ O) {
  const int b = blockIdx.x, tid = threadIdx.x;
  if (b < 256) {
    int idx = b * 256 + tid;
    int o = idx >> 4, r = idx & 15;
    g_W2[idx] = O[o] * U[idx] * S[r];
  } else if (b < 512) {
    const int p = b - 256, r = p >> 4, r2 = p & 15;
    const float4* va = (const float4*)(V + r  * K_DIM);
    const float4* vb = (const float4*)(V + r2 * K_DIM);
    float s = 0.f;
    for (int i = tid; i < 1024; i += 256) {
      float4 a = va[i], c = vb[i];
      s += a.x * c.x + a.y * c.y + a.z * c.z + a.w * c.w;
    }
    __shared__ float red[256];
    red[tid] = s; __syncthreads();
#pragma unroll
    for (int st = 128; st; st >>= 1) {
      if (tid < st) red[tid] += red[tid + st];
      __syncthreads();
    }
    if (tid == 0) g_G[p] = red[0];
  } else {
#pragma unroll
    for (int j = 0; j < 8; ++j) {
      int idx = (b - 512) * 8192 + j * 1024 + tid * 4;
      float4 v = *(const float4*)(V + idx);
      union { __half2 h[2]; uint2 u; } P;
      P.h[0] = __floats2half2_rn(v.x, v.y);
      P.h[1] = __floats2half2_rn(v.z, v.w);
      *(uint2*)(g_vh + idx) = P.u;
    }
  }
}

__global__ void __launch_bounds__(256) k_t() {
  __shared__ __align__(16) __half As[2][128 * 72];
  __shared__ __align__(16) __half Vs[2][16 * 72];
  const int tid = threadIdx.x, lane = tid & 31, warp = tid >> 5;
  const bool isw = blockIdx.x >= 128;
  const int row0 = (isw ? (int)blockIdx.x - 128 : (int)blockIdx.x) * 128;
  const __half* A = isw ? g_wh_h : g_xh_h;
  float* outp = isw ? g_d : g_t;

  auto load = [&](int s, int kc) {
    const int k0 = kc * 64;
    const uint32_t ab = smem_u32(&As[s][0]);
#pragma unroll
    for (int i = 0; i < 4; ++i) {
      int c = i * 256 + tid, r = c >> 3, q = c & 7;
      cpa16(ab + (uint32_t)(r * 72 + q * 8) * 2,
            A + (size_t)(row0 + r) * K_DIM + k0 + q * 8);
    }
    if (tid < 128) {
      int r = tid >> 3, q = tid & 7;
      cpa16(smem_u32(&Vs[s][0]) + (uint32_t)(r * 72 + q * 8) * 2,
            g_vh + r * K_DIM + k0 + q * 8);
    }
  };

  float acc[2][4];
#pragma unroll
  for (int i = 0; i < 2; ++i)
#pragma unroll
    for (int e = 0; e < 4; ++e) acc[i][e] = 0.f;

  load(0, 0);
  asm volatile("cp.async.commit_group;" ::: "memory");

  const int arow = lane & 15, acol = (lane >> 4) << 3;
  const int brow = (lane & 7) + ((lane >> 4) << 3), bcol = ((lane >> 3) & 1) << 3;

  for (int kc = 0; kc < 64; ++kc) {
    if (kc + 1 < 64) load((kc + 1) & 1, kc + 1);
    asm volatile("cp.async.commit_group;" ::: "memory");
    asm volatile("cp.async.wait_group 1;" ::: "memory");
    __syncthreads();
    const uint32_t aB = smem_u32(&As[kc & 1][0]);
    const uint32_t bB = smem_u32(&Vs[kc & 1][0]);
#pragma unroll
    for (int kk = 0; kk < 4; ++kk) {
      uint32_t a[4], bt[4];
      LDMX4(a, aB + (uint32_t)((warp * 16 + arow) * 72 + kk * 16 + acol) * 2);
      LDMX4(bt, bB + (uint32_t)(brow * 72 + kk * 16 + bcol) * 2);
      uint32_t b0[2] = {bt[0], bt[1]}, b1[2] = {bt[2], bt[3]};
      MMA16816(acc[0], a, b0);
      MMA16816(acc[1], a, b1);
    }
    __syncthreads();
  }

  const int r1 = row0 + warp * 16 + (lane >> 2);
#pragma unroll
  for (int nt = 0; nt < 2; ++nt) {
    const int c = nt * 8 + 2 * (lane & 3);
    *(float2*)&outp[(size_t)r1 * 16 + c]       = make_float2(acc[nt][0], acc[nt][1]);
    *(float2*)&outp[(size_t)(r1 + 8) * 16 + c] = make_float2(acc[nt][2], acc[nt][3]);
  }
}

__global__ void k_scale(const float* __restrict__ mag) {
  int o = blockIdx.x * 256 + threadIdx.x;
  float w2[16];
#pragma unroll
  for (int r = 0; r < 16; ++r) w2[r] = g_W2[o * 16 + r];
  float n2 = g_nb[o];
#pragma unroll
  for (int r = 0; r < 16; ++r) n2 += 2.f * w2[r] * g_d[o * 16 + r];
#pragma unroll
  for (int r = 0; r < 16; ++r) {
    float gr = 0.f;
#pragma unroll
    for (int r2 = 0; r2 < 16; ++r2) gr += g_G[r * 16 + r2] * w2[r2];
    n2 += w2[r] * gr;
  }
  float sc = mag[o] / sqrtf(n2);
  g_sm1[o] = sc - 1.f;
#pragma unroll
  for (int r = 0; r < 16; ++r) g_W2s[o * 16 + r] = sc * w2[r];
}

// ============================================================
// k_gemm_h: fp16 mma.sync, TMA producer (2 req/kt vs 3072 LDGSTS),
// 4-stage mbarrier ring, SW128 swizzled tiles, fused DoRA epilogue.
// ============================================================
#define BMt 256
#define BNt 128
#define BKh 64
#define NKTt (K_DIM / BKh)               // 64
#define A_BYTES (BMt * 128)              // 32768 (256 rows x 128B)
#define B_BYTES (BNt * 128)              // 16384
#define STAGE_B (A_BYTES + B_BYTES)      // 49152
#define NSTG 4
#define GEMM_SMEM (NSTG * STAGE_B + 1024)  // 197632

__global__ void __launch_bounds__(256, 1)
k_gemm_h(const __grid_constant__ CUtensorMap mapA,
         const __grid_constant__ CUtensorMap mapB,
         float* __restrict__ out) {
  extern __shared__ __align__(16) uint8_t dynsm[];
  __shared__ __align__(8) uint64_t s_bar[8];  // full[4], empty[4]

  const int tid  = threadIdx.x;
  const int lane = tid & 31;
  const int warp = tid >> 5;
  const int m_base = (warp >> 1) * 64;
  const int n_base = (warp & 1) * 64;
  const int bM = blockIdx.y * BMt;
  const int bN = blockIdx.x * BNt;

  const uint32_t raw = smem_u32(dynsm);
  const uint32_t smb = (raw + 1023u) & ~1023u;
  const uint32_t barb = smem_u32(s_bar);

  if (tid == 0) {
#pragma unroll
    for (int s = 0; s < 4; ++s) {
      bar_init(barb + s * 8, 1);          // full: tx-based
      bar_init(barb + 32 + s * 8, 256);   // empty: all threads arrive
    }
  }
  __syncthreads();
#pragma unroll
  for (int s = 0; s < 4; ++s) bar_arrive(barb + 32 + s * 8);  // pre-arm empties

  // prefill stages 0..2
  if (tid == 0) {
#pragma unroll
    for (int p = 0; p < 3; ++p) {
      const uint32_t fb = barb + p * 8;
      bar_wait(barb + 32 + p * 8, 0);
      bar_expect_tx(fb, STAGE_B);
      const uint32_t base = smb + p * STAGE_B;
      tma2d(base,           &mapA, p * BKh, bM, fb);
      tma2d(base + A_BYTES, &mapB, p * BKh, bN, fb);
    }
  }

  float acc[4][8][4];
#pragma unroll
  for (int i = 0; i < 4; ++i)
#pragma unroll
    for (int j = 0; j < 8; ++j)
#pragma unroll
      for (int e = 0; e < 4; ++e) acc[i][j][e] = 0.f;

  const int arow = lane & 15;
  const int ahalf = lane >> 4;                       // 0/1
  const int brow = (lane & 7) + ((lane >> 4) << 3);
  const int bhalf = (lane >> 3) & 1;

  for (int kt = 0; kt < NKTt; ++kt) {
    const int p = kt + 3;
    if (tid == 0 && p < NKTt) {
      const int sp = p & 3;
      const uint32_t fb = barb + sp * 8;
      bar_wait(barb + 32 + sp * 8, (p >> 2) & 1);
      bar_expect_tx(fb, STAGE_B);
      const uint32_t base = smb + sp * STAGE_B;
      tma2d(base,           &mapA, p * BKh, bM, fb);
      tma2d(base + A_BYTES, &mapB, p * BKh, bN, fb);
    }
    const int s = kt & 3;
    bar_wait(barb + s * 8, (kt >> 2) & 1);

    const uint32_t aB = smb + s * STAGE_B;
    const uint32_t bB = aB + A_BYTES;
#pragma unroll
    for (int kk = 0; kk < 4; ++kk) {
      uint32_t ah[4][4], bh[8][2];
#pragma unroll
      for (int mt = 0; mt < 4; ++mt) {
        const uint32_t off = (uint32_t)((m_base + mt * 16 + arow) * 128 +
                                        (kk * 2 + ahalf) * 16);
        LDMX4(ah[mt], aB + SWZ(off));
      }
#pragma unroll
      for (int pp = 0; pp < 4; ++pp) {
        const uint32_t off = (uint32_t)((n_base + pp * 16 + brow) * 128 +
                                        (kk * 2 + bhalf) * 16);
        uint32_t r[4];
        LDMX4(r, bB + SWZ(off));
        bh[2 * pp][0] = r[0]; bh[2 * pp][1] = r[1];
        bh[2 * pp + 1][0] = r[2]; bh[2 * pp + 1][1] = r[3];
      }
#pragma unroll
      for (int mt = 0; mt < 4; ++mt)
#pragma unroll
        for (int nt = 0; nt < 8; ++nt)
          MMA16816(acc[mt][nt], ah[mt], bh[nt]);
    }
    bar_arrive(barb + 32 + s * 8);
  }

  __syncthreads();

  // ---------------- fused DoRA epilogue ----------------
  float* smf = (float*)(dynsm + (smb - raw));
  float* st = smf;                  // t tile  [256][17]
  float* sw = smf + 256 * 17;       // W2s     [128*16]
  float* ss = sw + 128 * 16;        // scale-1 [128]
  for (int i = tid; i < 256 * 16; i += 256) st[(i >> 4) * 17 + (i & 15)] = g_t[(size_t)bM * 16 + i];
  for (int i = tid; i < 128 * 16; i += 256) sw[i] = g_W2s[(size_t)bN * 16 + i];
  if (tid < 128) ss[tid] = g_sm1[bN + tid];
  __syncthreads();

#pragma unroll
  for (int nt = 0; nt < 8; ++nt) {
    const int c = n_base + nt * 8 + 2 * (lane & 3);
    const float s0 = ss[c], s1 = ss[c + 1];
#pragma unroll
    for (int mt = 0; mt < 4; ++mt) {
      acc[mt][nt][0] *= s0; acc[mt][nt][1] *= s1;
      acc[mt][nt][2] *= s0; acc[mt][nt][3] *= s1;
    }
  }
#pragma unroll
  for (int r = 0; r < 16; ++r) {
    float tr[8], wr[16];
#pragma unroll
    for (int mt = 0; mt < 4; ++mt) {
      tr[mt * 2]     = st[(m_base + mt * 16 +     (lane >> 2)) * 17 + r];
      tr[mt * 2 + 1] = st[(m_base + mt * 16 + 8 + (lane >> 2)) * 17 + r];
    }
#pragma unroll
    for (int nt = 0; nt < 8; ++nt) {
      wr[nt * 2]     = sw[(n_base + nt * 8 + 2 * (lane & 3))     * 16 + r];
      wr[nt * 2 + 1] = sw[(n_base + nt * 8 + 2 * (lane & 3) + 1) * 16 + r];
    }
#pragma unroll
    for (int mt = 0; mt < 4; ++mt)
#pragma unroll
      for (int nt = 0; nt < 8; ++nt) {
        acc[mt][nt][0] += tr[mt * 2]     * wr[nt * 2];
        acc[mt][nt][1] += tr[mt * 2]     * wr[nt * 2 + 1];
        acc[mt][nt][2] += tr[mt * 2 + 1] * wr[nt * 2];
        acc[mt][nt][3] += tr[mt * 2 + 1] * wr[nt * 2 + 1];
      }
  }
#pragma unroll
  for (int mt = 0; mt < 4; ++mt)
#pragma unroll
    for (int h = 0; h < 2; ++h) {
      const int gm = bM + m_base + mt * 16 + h * 8 + (lane >> 2);
#pragma unroll
      for (int nt = 0; nt < 8; ++nt) {
        const int gn = bN + n_base + nt * 8 + 2 * (lane & 3);
        float2 v = make_float2(acc[mt][nt][h * 2], acc[mt][nt][h * 2 + 1]);
        *(float2*)(out + (size_t)gm * N_DIM + gn) = v;
      }
    }
}

// ============================================================
typedef CUresult (*EncTiledFn)(
    CUtensorMap*, CUtensorMapDataType, cuuint32_t, void*,
    const cuuint64_t*, const cuuint64_t*, const cuuint32_t*, const cuuint32_t*,
    CUtensorMapInterleave, CUtensorMapSwizzle, CUtensorMapL2promotion,
    CUtensorMapFloatOOBfill);

extern "C" void kernel_launch(void* const* d_in, const int* in_sizes, int n_in,
                              void* d_out, int out_size) {
  (void)in_sizes; (void)n_in; (void)out_size;
  const float* x   = (const float*)d_in[0];
  const float* U   = (const float*)d_in[1];
  const float* V   = (const float*)d_in[2];
  const float* S   = (const float*)d_in[3];
  const float* O   = (const float*)d_in[4];
  const float* mag = (const float*)d_in[5];
  const float* W   = (const float*)d_in[6];
  float* out = (float*)d_out;

  cudaFuncSetAttribute(k_gemm_h, cudaFuncAttributeMaxDynamicSharedMemorySize, GEMM_SMEM);

  // build TMA descriptors (host-side, capture-safe, no allocations)
  void* fn = nullptr;
  cudaDriverEntryPointQueryResult qr;
  cudaGetDriverEntryPointByVersion("cuTensorMapEncodeTiled", &fn, 12000,
                                   cudaEnableDefault, &qr);
  EncTiledFn enc = (EncTiledFn)fn;
  void *pxh, *pwh;
  cudaGetSymbolAddress(&pxh, g_xh_h);
  cudaGetSymbolAddress(&pwh, g_wh_h);

  CUtensorMap mA, mB;
  {
    cuuint64_t dims[2]  = {(cuuint64_t)K_DIM, (cuuint64_t)M_DIM};
    cuuint64_t strd[1]  = {(cuuint64_t)K_DIM * 2};
    cuuint32_t box[2]   = {BKh, BMt};
    cuuint32_t es[2]    = {1, 1};
    enc(&mA, CU_TENSOR_MAP_DATA_TYPE_FLOAT16, 2, pxh, dims, strd, box, es,
        CU_TENSOR_MAP_INTERLEAVE_NONE, CU_TENSOR_MAP_SWIZZLE_128B,
        CU_TENSOR_MAP_L2_PROMOTION_L2_128B, CU_TENSOR_MAP_FLOAT_OOB_FILL_NONE);
  }
  {
    cuuint64_t dims[2]  = {(cuuint64_t)K_DIM, (cuuint64_t)N_DIM};
    cuuint64_t strd[1]  = {(cuuint64_t)K_DIM * 2};
    cuuint32_t box[2]   = {BKh, BNt};
    cuuint32_t es[2]    = {1, 1};
    enc(&mB, CU_TENSOR_MAP_DATA_TYPE_FLOAT16, 2, pwh, dims, strd, box, es,
        CU_TENSOR_MAP_INTERLEAVE_NONE, CU_TENSOR_MAP_SWIZZLE_128B,
        CU_TENSOR_MAP_L2_PROMOTION_L2_128B, CU_TENSOR_MAP_FLOAT_OOB_FILL_NONE);
  }

  const int n8x = (M_DIM * K_DIM) / 8;
  k_split_x<<<n8x / 256, 256>>>(x, n8x);          // 1
  k_split_w_nb<<<N_DIM / 8, 256>>>(W);            // 2
  k_prep<<<520, 256>>>(U, V, S, O);               // 3
  k_t<<<160, 256>>>();                            // 4
  k_scale<<<N_DIM / 256, 256>>>(mag);             // 5
  k_gemm_h<<<dim3(N_DIM / BNt, M_DIM / BMt), 256, GEMM_SMEM>>>(mA, mB, out);  // 6
}